// round 15
// baseline (speedup 1.0000x reference)
#include <cuda_runtime.h>
#include <cstdint>
#include <math.h>

#define T_STEPS 100
#define NPIX    784
#define NPAIR   392
#define NOUT    10
#define LSTR    42           /* LUT stride words: 4*10 + 2 pad; 8B-aligned */
#define WARPS_PB 28
#define THREADS  (WARPS_PB * 32)
#define NBATCH   16384

// Integer add forced onto the FMA pipe (IMAD): d = a*one + b, one==1 at runtime
// but opaque to the compiler so it cannot strength-reduce to IADD3.
__device__ __forceinline__ uint32_t madd(uint32_t a, uint32_t b, uint32_t one) {
    uint32_t d;
    asm("mad.lo.u32 %0, %1, %2, %3;" : "=r"(d) : "r"(a), "r"(one), "r"(b));
    return d;
}

struct TFK { uint32_t k0, k1, k2, i1, i2, i3, i4, i5; };

// JAX threefry2x32, exact; x0 initial = 0; injection consts precomputed per t.
// k1x = K.k1 + counter_offset (hoisted per timestep): x1 = ctr + (k1 + delta).
__device__ __forceinline__ uint2 tf2x32(const TFK& K, uint32_t ctr, uint32_t k1x,
                                        uint32_t one) {
    uint32_t x0 = K.k0;
    uint32_t x1 = madd(ctr, k1x, one);
#define R(r) { x0 = madd(x0, x1, one); x1 = __funnelshift_l(x1, x1, (r)); x1 ^= x0; }
    R(13) R(15) R(26) R(6)
    x0 = madd(x0, K.k1, one); x1 = madd(x1, K.i1, one);
    R(17) R(29) R(16) R(24)
    x0 = madd(x0, K.k2, one); x1 = madd(x1, K.i2, one);
    R(13) R(15) R(26) R(6)
    x0 = madd(x0, K.k0, one); x1 = madd(x1, K.i3, one);
    R(17) R(29) R(16) R(24)
    x0 = madd(x0, K.k1, one); x1 = madd(x1, K.i4, one);
    R(13) R(15) R(26) R(6)
    x0 = madd(x0, K.k2, one); x1 = madd(x1, K.i5, one);
#undef R
    return make_uint2(x0, x1);
}

__device__ __forceinline__ uint32_t smem_u32(const void* p) {
    uint32_t a;
    asm("{ .reg .u64 t; cvta.to.shared.u64 t, %1; cvt.u32.u64 %0, t; }"
        : "=r"(a) : "l"(p));
    return a;
}

// mask = 0xFFFFFFFF if a < b else 0 (single SET op)
__device__ __forceinline__ uint32_t ltmask(uint32_t a, uint32_t b) {
    uint32_t m;
    asm("set.lt.u32.u32 %0, %1, %2;" : "=r"(m) : "r"(a), "r"(b));
    return m;
}

// lp = base + s0*(-40) + s1*(-80): two IMADs with immediate multipliers (fma pipe)
__device__ __forceinline__ uint32_t lutaddr(uint32_t base, uint32_t s0, uint32_t s1) {
    uint32_t t, d;
    asm("mad.lo.u32 %0, %1, -40, %2;" : "=r"(t) : "r"(s0), "r"(base));
    asm("mad.lo.u32 %0, %1, -80, %2;" : "=r"(d) : "r"(s1), "r"(t));
    return d;
}

// pre-shifted saturated threshold: spike <=> bits < (ceil(x*2^23) << 9)
__device__ __forceinline__ uint32_t thval(float xv) {
    double d = (double)xv * 8388608.0;
    uint32_t t = (uint32_t)ceil(d);
    return (t >= 8388608u) ? 0xFFFFFFFFu : (t << 9);
}

// smem: keys (800B) | pair-LUT (392*42*4 = 65856B)
//       | quad thresholds xq: 28 warps * 7 slots * 32 lanes * 16B = 100352B
//         slot j (j<6) lane l = {th[2l+128j], th[2l+128j+1], th[2l+128j+64], th[2l+128j+65]}
//         slot 6 = tail thresholds (lanes 0-7), also the j=5 prefetch target
#define SM_KEYS  0
#define SM_LUT   800
#define SM_XQ    (SM_LUT + NPAIR * LSTR * 4)
#define SM_TOTAL (SM_XQ + WARPS_PB * 7 * 32 * 16)

__global__ void __launch_bounds__(THREADS, 1)
snn_kernel(const float* __restrict__ x, const float* __restrict__ W,
           float* __restrict__ out) {
    extern __shared__ unsigned char sm[];
    uint2* keys = (uint2*)(sm + SM_KEYS);
    float* LUT  = (float*)(sm + SM_LUT);
    uint4* xq   = (uint4*)(sm + SM_XQ);

    const int tid  = threadIdx.x;
    const int warp = tid >> 5;
    const int lane = tid & 31;
    const int b    = blockIdx.x * WARPS_PB + warp;
    const bool active = (b < NBATCH);
    const uint32_t base = active ? (uint32_t)b * NPIX : 0u;
    const uint32_t one  = (base >> 24) | 1u;     // == 1, opaque to compiler

    // --- per-timestep keys: split(key(42),100) partitionable/foldlike ---
    if (tid < T_STEPS) {
        TFK K0;
        K0.k0 = 0u; K0.k1 = 42u; K0.k2 = 0u ^ 42u ^ 0x1BD11BDAu;
        K0.i1 = K0.k2 + 1u; K0.i2 = K0.k0 + 2u; K0.i3 = K0.k1 + 3u;
        K0.i4 = K0.k2 + 4u; K0.i5 = K0.k0 + 5u;
        keys[tid] = tf2x32(K0, (uint32_t)tid, K0.k1, one);
    }

    // --- pair subset-sum LUT: LUT[g*42 + m*10 + o] ---
    for (int i = tid; i < NPAIR * 4 * NOUT; i += THREADS) {
        int g = i / 40;
        int r = i - g * 40;
        int m = r / 10, o = r - m * 10;
        float s = 0.0f;
        if (m & 1) s += W[o * NPIX + 2 * g];
        if (m & 2) s += W[o * NPIX + 2 * g + 1];
        LUT[g * LSTR + m * 10 + o] = s;
    }

    // --- quad-interleaved thresholds (one LDS.128 per mainloop iter) ---
    if (active) {
        uint4* wq = xq + warp * (7 * 32);
        const float* xb = x + (size_t)b * NPIX;
#pragma unroll
        for (int j = 0; j < 6; j++) {
            int p0 = 2 * lane + 128 * j;
            wq[j * 32 + lane] = make_uint4(thval(xb[p0]),      thval(xb[p0 + 1]),
                                           thval(xb[p0 + 64]), thval(xb[p0 + 65]));
        }
        uint4 tq = make_uint4(0u, 0u, 0u, 0u);
        if (lane < 8) {
            int p0 = 768 + 2 * lane;
            tq.x = thval(xb[p0]);
            tq.y = thval(xb[p0 + 1]);
        }
        wq[6 * 32 + lane] = tq;
    }
    __syncthreads();
    if (!active) return;

    const uint32_t th_s0  = smem_u32(xq + warp * (7 * 32)) + (uint32_t)lane * 16u;
    const uint32_t lut_l0 = smem_u32(LUT) + (uint32_t)lane * (LSTR * 4);

    float v[NOUT], cnt[NOUT];
#pragma unroll
    for (int o = 0; o < NOUT; o++) { v[o] = 0.f; cnt[o] = 0.f; }

    for (int t = 0; t < T_STEPS; t++) {
        const uint2 kk = keys[t];
        TFK K;
        K.k0 = kk.x; K.k1 = kk.y; K.k2 = K.k0 ^ K.k1 ^ 0x1BD11BDAu;
        K.i1 = K.k2 + 1u; K.i2 = K.k0 + 2u; K.i3 = K.k1 + 3u;
        K.i4 = K.k2 + 4u; K.i5 = K.k0 + 5u;
        const uint32_t k1p0  = K.k1;
        const uint32_t k1p1  = K.k1 + 1u;
        const uint32_t k1p64 = K.k1 + 64u;
        const uint32_t k1p65 = K.k1 + 65u;

        unsigned long long acc2[5];
#pragma unroll
        for (int k = 0; k < 5; k++) acc2[k] = 0ULL;

        // 2 pairs per lane per iter: g = lane + 64j and g + 32
        uint32_t cA     = base + 2u * (uint32_t)lane;
        uint32_t th_ptr = th_s0;
        uint32_t lut_g  = lut_l0;

        uint4 th;
        asm("ld.shared.v4.u32 {%0,%1,%2,%3}, [%4];"
            : "=r"(th.x), "=r"(th.y), "=r"(th.z), "=r"(th.w) : "r"(th_ptr));

        // 392 pairs = 6 iters * 64 pairs + tail of 8 (lanes 0-7)
#pragma unroll 3
        for (int j = 0; j < 6; j++) {
            // 4 independent hash chains; counter offsets ride in the keys
            uint2 rA = tf2x32(K, cA, k1p0,  one);
            uint2 rB = tf2x32(K, cA, k1p1,  one);
            uint2 rC = tf2x32(K, cA, k1p64, one);
            uint2 rD = tf2x32(K, cA, k1p65, one);

            // single quad prefetch of next iteration's thresholds
            // (j=5 fetch lands on slot 6 = the tail's thresholds)
            uint4 tn;
            asm("ld.shared.v4.u32 {%0,%1,%2,%3}, [%4+512];"
                : "=r"(tn.x), "=r"(tn.y), "=r"(tn.z), "=r"(tn.w) : "r"(th_ptr));

            uint32_t sA0 = ltmask(rA.x ^ rA.y, th.x);
            uint32_t sA1 = ltmask(rB.x ^ rB.y, th.y);
            uint32_t sB0 = ltmask(rC.x ^ rC.y, th.z);
            uint32_t sB1 = ltmask(rD.x ^ rD.y, th.w);
            uint32_t lpA = lutaddr(lut_g, sA0, sA1);         // pair A LUT row
            uint32_t lpB = lutaddr(lut_g, sB0, sB1);         // pair B row base (-ofs)
#pragma unroll
            for (int k = 0; k < 5; k++) {
                unsigned long long wA, wB;
                asm("ld.shared.b64 %0, [%1];" : "=l"(wA) : "r"(lpA + 8u * k));
                asm("add.rn.f32x2 %0, %1, %2;" : "=l"(acc2[k]) : "l"(acc2[k]), "l"(wA));
                asm("ld.shared.b64 %0, [%1+5376];" : "=l"(wB) : "r"(lpB + 8u * k)); // +32*42*4
                asm("add.rn.f32x2 %0, %1, %2;" : "=l"(acc2[k]) : "l"(acc2[k]), "l"(wB));
            }

            th = tn;
            cA     = madd(cA, 128u, one);
            th_ptr = madd(th_ptr, 512u, one);
            lut_g  = madd(lut_g, 64u * LSTR * 4u, one);
        }
        if (lane < 8) {   // tail: pair g = 384 + lane; thresholds in th.x/.y
            uint2 rA = tf2x32(K, cA, k1p0, one);
            uint2 rB = tf2x32(K, cA, k1p1, one);
            uint32_t s0 = ltmask(rA.x ^ rA.y, th.x);
            uint32_t s1 = ltmask(rB.x ^ rB.y, th.y);
            uint32_t lp = lutaddr(lut_g, s0, s1);
#pragma unroll
            for (int k = 0; k < 5; k++) {
                unsigned long long w;
                asm("ld.shared.b64 %0, [%1];" : "=l"(w) : "r"(lp + 8u * k));
                asm("add.rn.f32x2 %0, %1, %2;" : "=l"(acc2[k]) : "l"(acc2[k]), "l"(w));
            }
        }

        // packed butterfly: accumulators stay f32x2; mov.b64 splits are
        // register-pair aliases (free); 2 SHFL + 1 FADD2 per reg per step.
#pragma unroll
        for (int off = 16; off > 0; off >>= 1) {
#pragma unroll
            for (int k = 0; k < 5; k++) {
                uint32_t lo, hi;
                asm("mov.b64 {%0, %1}, %2;" : "=r"(lo), "=r"(hi) : "l"(acc2[k]));
                lo = __shfl_xor_sync(0xFFFFFFFFu, lo, off);
                hi = __shfl_xor_sync(0xFFFFFFFFu, hi, off);
                unsigned long long other;
                asm("mov.b64 %0, {%1, %2};" : "=l"(other) : "r"(lo), "r"(hi));
                asm("add.rn.f32x2 %0, %1, %2;" : "=l"(acc2[k]) : "l"(acc2[k]), "l"(other));
            }
        }

        float acc[NOUT];
#pragma unroll
        for (int k = 0; k < 5; k++)
            asm("mov.b64 {%0, %1}, %2;" : "=f"(acc[2 * k]), "=f"(acc[2 * k + 1]) : "l"(acc2[k]));

        // LIF: v += (I - v)/2 ; spike if v>=1 ; hard reset (bit-exact vs XLA)
#pragma unroll
        for (int o = 0; o < NOUT; o++) {
            float nv = fmaf(acc[o] - v[o], 0.5f, v[o]);
            if (nv >= 1.0f) { cnt[o] += 1.0f; nv = 0.0f; }
            v[o] = nv;
        }
    }

    if (lane == 0) {
#pragma unroll
        for (int o = 0; o < NOUT; o++)
            out[(size_t)b * NOUT + o] = cnt[o] / 100.0f;
    }
}

extern "C" void kernel_launch(void* const* d_in, const int* in_sizes, int n_in,
                              void* d_out, int out_size) {
    const float* x = (const float*)d_in[0];   // [16384,1,28,28] f32
    const float* W = (const float*)d_in[1];   // [10,784] f32
    float* out = (float*)d_out;               // [16384,10] f32

    const int nblocks = (NBATCH + WARPS_PB - 1) / WARPS_PB;   // 586
    cudaFuncSetAttribute(snn_kernel, cudaFuncAttributeMaxDynamicSharedMemorySize,
                         SM_TOTAL);
    snn_kernel<<<nblocks, THREADS, SM_TOTAL>>>(x, W, out);
}